// round 1
// baseline (speedup 1.0000x reference)
#include <cuda_runtime.h>
#include <mma.h>
#include <cstdint>
#include <cstddef>

using namespace nvcuda;

#define Bv   2
#define Sv   2048
#define Hv   2048
#define NHv  16
#define HDv  128
#define BSv  256
#define Mtot (Bv * Sv)
#define ATT_SCALE 0.08838834764831843f  // 1/sqrt(128)

// Scratch buffers (allocation-free rule: __device__ globals)
__device__ float g_q[(size_t)Mtot * Hv];
__device__ float g_k[(size_t)Mtot * Hv];
__device__ float g_v[(size_t)Mtot * Hv];
__device__ float g_o[(size_t)Mtot * Hv];

__device__ __forceinline__ float to_tf32(float x) {
    float y;
    asm("cvt.rna.tf32.f32 %0, %1;" : "=f"(y) : "f"(x));
    return y;
}

// =====================================================================
// GEMM: C[M,N] = A[M,K] @ Bw[N,K]^T   (both operands K-contiguous)
// tf32 wmma m16n16k8, tile 128x128x32, 256 threads (8 warps as 4x2)
// =====================================================================
#define GBM 128
#define GBN 128
#define GBK 32
#define GSTR 40   // 32 + 8 pad (keeps 16B-multiple ldm, softens bank conflicts)

__global__ void __launch_bounds__(256) gemm_tn(
    const float* __restrict__ A, const float* __restrict__ Bw,
    float* __restrict__ C, int M, int N, int K)
{
    extern __shared__ __align__(16) float sm[];
    float* shA = sm;                 // [GBM][GSTR]
    float* shB = sm + GBM * GSTR;    // [GBN][GSTR]

    const int tid = threadIdx.x;
    const int wid = tid >> 5;
    const int m0 = blockIdx.y * GBM;
    const int n0 = blockIdx.x * GBN;
    const int wm = wid & 3;   // 4 warp rows, 32 m each
    const int wn = wid >> 2;  // 2 warp cols, 64 n each

    wmma::fragment<wmma::accumulator, 16, 16, 8, float> acc[2][4];
#pragma unroll
    for (int i = 0; i < 2; i++)
#pragma unroll
        for (int j = 0; j < 4; j++) wmma::fill_fragment(acc[i][j], 0.0f);

    for (int k0 = 0; k0 < K; k0 += GBK) {
#pragma unroll
        for (int i = 0; i < 4; i++) {
            int slot = tid + i * 256;       // 1024 float4 slots
            int r = slot >> 3, c4 = slot & 7;
            float4 v = *(const float4*)(A + (size_t)(m0 + r) * K + k0 + c4 * 4);
            float* d = shA + r * GSTR + c4 * 4;
            d[0] = to_tf32(v.x); d[1] = to_tf32(v.y);
            d[2] = to_tf32(v.z); d[3] = to_tf32(v.w);
        }
#pragma unroll
        for (int i = 0; i < 4; i++) {
            int slot = tid + i * 256;
            int r = slot >> 3, c4 = slot & 7;
            float4 v = *(const float4*)(Bw + (size_t)(n0 + r) * K + k0 + c4 * 4);
            float* d = shB + r * GSTR + c4 * 4;
            d[0] = to_tf32(v.x); d[1] = to_tf32(v.y);
            d[2] = to_tf32(v.z); d[3] = to_tf32(v.w);
        }
        __syncthreads();

#pragma unroll
        for (int kk = 0; kk < GBK; kk += 8) {
            wmma::fragment<wmma::matrix_a, 16, 16, 8, wmma::precision::tf32, wmma::row_major> af[2];
#pragma unroll
            for (int i = 0; i < 2; i++)
                wmma::load_matrix_sync(af[i], shA + (wm * 32 + i * 16) * GSTR + kk, GSTR);
#pragma unroll
            for (int j = 0; j < 4; j++) {
                wmma::fragment<wmma::matrix_b, 16, 16, 8, wmma::precision::tf32, wmma::col_major> bf;
                wmma::load_matrix_sync(bf, shB + (wn * 64 + j * 16) * GSTR + kk, GSTR);
#pragma unroll
                for (int i = 0; i < 2; i++)
                    wmma::mma_sync(acc[i][j], af[i], bf, acc[i][j]);
            }
        }
        __syncthreads();
    }

#pragma unroll
    for (int i = 0; i < 2; i++)
#pragma unroll
        for (int j = 0; j < 4; j++)
            wmma::store_matrix_sync(
                C + (size_t)(m0 + wm * 32 + i * 16) * N + n0 + wn * 64 + j * 16,
                acc[i][j], N, wmma::mem_row_major);
}

// =====================================================================
// Attention with per-block softmax (each 256-key block independent).
// CTA = (64 queries) x (1 head). Loops kv blocks j <= bi.
//   S[64,256] built from 4 sub-GEMMs against 64-row K subtiles,
//   per-block softmax (rowmax/exp/rowsum over the 256 keys of this block),
//   O += P @ V accumulated in fragments; final O /= (bi+1+1e-6).
// =====================================================================
#define QT  64
#define AST 136   // 128 + 8 pad
#define SST 264   // 256 + 8 pad

__global__ void __launch_bounds__(256) attn_kernel()
{
    extern __shared__ __align__(16) float sm[];
    float* shQ  = sm;                  // [64][AST]
    float* shKV = shQ + QT * AST;      // [64][AST]
    float* shS  = shKV + QT * AST;     // [64][SST]

    const int tid = threadIdx.x;
    const int wid = tid >> 5;
    const int qt = blockIdx.x;   // 0..31
    const int h  = blockIdx.y;   // 0..15
    const int b  = blockIdx.z;   // 0..1
    const int qbase = qt * QT;
    const int bi = qbase >> 8;   // 256-key block index of this query tile

    // Load Q tile (tf32-rounded)
    const float* Qp = g_q + ((size_t)b * Sv + qbase) * Hv + h * HDv;
#pragma unroll
    for (int i = 0; i < 8; i++) {
        int slot = tid + i * 256;            // 2048 float4 slots
        int r = slot >> 5, c4 = slot & 31;
        float4 v = *(const float4*)(Qp + (size_t)r * Hv + c4 * 4);
        float* d = shQ + r * AST + c4 * 4;
        d[0] = to_tf32(v.x); d[1] = to_tf32(v.y);
        d[2] = to_tf32(v.z); d[3] = to_tf32(v.w);
    }

    wmma::fragment<wmma::accumulator, 16, 16, 8, float> acc_o[2][2];
#pragma unroll
    for (int i = 0; i < 2; i++)
#pragma unroll
        for (int j = 0; j < 2; j++) wmma::fill_fragment(acc_o[i][j], 0.0f);

    const int wms = wid & 3,  wns = wid >> 2;  // S phase: 16 rows x 32 cols per warp
    const int wmo = wid & 1,  wno = wid >> 1;  // O phase: 32 rows x 32 cols per warp

    const int row  = tid >> 2;          // softmax: 4 threads per row
    const int part = tid & 3;
    const int qoff = (qbase & 255) + row;  // query position inside its 256-block

    for (int jb = 0; jb <= bi; jb++) {
        // ---- scores: S[:, sub*64 .. +64] = Q @ Ksub^T ----
        for (int sub = 0; sub < 4; sub++) {
            __syncthreads();  // prior consumers of shKV / shS done
            const float* Kp = g_k + ((size_t)b * Sv + jb * BSv + sub * 64) * Hv + h * HDv;
#pragma unroll
            for (int i = 0; i < 8; i++) {
                int slot = tid + i * 256;
                int r = slot >> 5, c4 = slot & 31;
                float4 v = *(const float4*)(Kp + (size_t)r * Hv + c4 * 4);
                float* d = shKV + r * AST + c4 * 4;
                d[0] = to_tf32(v.x); d[1] = to_tf32(v.y);
                d[2] = to_tf32(v.z); d[3] = to_tf32(v.w);
            }
            __syncthreads();

            wmma::fragment<wmma::accumulator, 16, 16, 8, float> accs[2];
            wmma::fill_fragment(accs[0], 0.0f);
            wmma::fill_fragment(accs[1], 0.0f);
#pragma unroll
            for (int k = 0; k < HDv; k += 8) {
                wmma::fragment<wmma::matrix_a, 16, 16, 8, wmma::precision::tf32, wmma::row_major> af;
                wmma::load_matrix_sync(af, shQ + (wms * 16) * AST + k, AST);
#pragma unroll
                for (int j = 0; j < 2; j++) {
                    wmma::fragment<wmma::matrix_b, 16, 16, 8, wmma::precision::tf32, wmma::col_major> bf;
                    wmma::load_matrix_sync(bf, shKV + (wns * 32 + j * 16) * AST + k, AST);
                    wmma::mma_sync(accs[j], af, bf, accs[j]);
                }
            }
#pragma unroll
            for (int j = 0; j < 2; j++)
                wmma::store_matrix_sync(
                    shS + (wms * 16) * SST + sub * 64 + wns * 32 + j * 16,
                    accs[j], SST, wmma::mem_row_major);
        }
        __syncthreads();  // all of S written

        // ---- per-block softmax over the 256 keys of block jb ----
        {
            float* srow = shS + row * SST + part * 64;
            const bool diag = (jb == bi);
            const int cbase = part * 64;

            float mx = -3.0e38f;
#pragma unroll 8
            for (int c = 0; c < 64; c++) {
                bool masked = diag && (cbase + c > qoff);
                float s = srow[c];
                if (!masked) mx = fmaxf(mx, s);
            }
            mx = fmaxf(mx, __shfl_xor_sync(0xffffffffu, mx, 1));
            mx = fmaxf(mx, __shfl_xor_sync(0xffffffffu, mx, 2));
            mx *= ATT_SCALE;

            float sumv = 0.0f;
#pragma unroll 8
            for (int c = 0; c < 64; c++) {
                bool masked = diag && (cbase + c > qoff);
                float p = masked ? 0.0f : __expf(srow[c] * ATT_SCALE - mx);
                srow[c] = p;
                sumv += p;
            }
            sumv += __shfl_xor_sync(0xffffffffu, sumv, 1);
            sumv += __shfl_xor_sync(0xffffffffu, sumv, 2);
            float inv = 1.0f / sumv;
#pragma unroll 8
            for (int c = 0; c < 64; c++) srow[c] = to_tf32(srow[c] * inv);
        }

        // ---- O += P @ Vsub ----
        for (int sub = 0; sub < 4; sub++) {
            __syncthreads();  // softmax done (sub 0) / prior PV readers of shKV done
            const float* Vp = g_v + ((size_t)b * Sv + jb * BSv + sub * 64) * Hv + h * HDv;
#pragma unroll
            for (int i = 0; i < 8; i++) {
                int slot = tid + i * 256;
                int r = slot >> 5, c4 = slot & 31;
                float4 v = *(const float4*)(Vp + (size_t)r * Hv + c4 * 4);
                float* d = shKV + r * AST + c4 * 4;
                d[0] = to_tf32(v.x); d[1] = to_tf32(v.y);
                d[2] = to_tf32(v.z); d[3] = to_tf32(v.w);
            }
            __syncthreads();

#pragma unroll
            for (int k = 0; k < 64; k += 8) {
                wmma::fragment<wmma::matrix_a, 16, 16, 8, wmma::precision::tf32, wmma::row_major> af[2];
#pragma unroll
                for (int i = 0; i < 2; i++)
                    wmma::load_matrix_sync(af[i], shS + (wmo * 32 + i * 16) * SST + sub * 64 + k, SST);
#pragma unroll
                for (int j = 0; j < 2; j++) {
                    wmma::fragment<wmma::matrix_b, 16, 16, 8, wmma::precision::tf32, wmma::row_major> bf;
                    wmma::load_matrix_sync(bf, shKV + k * AST + wno * 32 + j * 16, AST);
#pragma unroll
                    for (int i = 0; i < 2; i++)
                        wmma::mma_sync(acc_o[i][j], af[i], bf, acc_o[i][j]);
                }
            }
        }
    }

    // ---- epilogue: divide by (#blocks + 1e-6), store merged layout ----
    const float invc = 1.0f / ((float)(bi + 1) + 1e-6f);
#pragma unroll
    for (int i = 0; i < 2; i++)
#pragma unroll
        for (int j = 0; j < 2; j++) {
#pragma unroll
            for (int t = 0; t < acc_o[i][j].num_elements; t++)
                acc_o[i][j].x[t] *= invc;
            wmma::store_matrix_sync(
                g_o + ((size_t)(b * Sv + qbase + wmo * 32 + i * 16)) * Hv + h * HDv + wno * 32 + j * 16,
                acc_o[i][j], Hv, wmma::mem_row_major);
        }
}

// =====================================================================
// launch
// =====================================================================
extern "C" void kernel_launch(void* const* d_in, const int* in_sizes, int n_in,
                              void* d_out, int out_size)
{
    const float* X  = (const float*)d_in[0];
    const float* Wq = (const float*)d_in[1];
    const float* Wk = (const float*)d_in[2];
    const float* Wv = (const float*)d_in[3];
    const float* Wo = (const float*)d_in[4];
    float* out = (float*)d_out;

    float *q, *k, *v, *o;
    cudaGetSymbolAddress((void**)&q, g_q);
    cudaGetSymbolAddress((void**)&k, g_k);
    cudaGetSymbolAddress((void**)&v, g_v);
    cudaGetSymbolAddress((void**)&o, g_o);

    const size_t gemm_smem = (size_t)(GBM * GSTR + GBN * GSTR) * sizeof(float);   // 40960
    const size_t attn_smem = (size_t)(2 * QT * AST + QT * SST) * sizeof(float);   // 137216

    cudaFuncSetAttribute(gemm_tn, cudaFuncAttributeMaxDynamicSharedMemorySize, (int)gemm_smem);
    cudaFuncSetAttribute(attn_kernel, cudaFuncAttributeMaxDynamicSharedMemorySize, (int)attn_smem);

    dim3 blk(256);
    dim3 gg(Hv / GBN, Mtot / GBM);   // (16, 32)

    gemm_tn<<<gg, blk, gemm_smem>>>(X, Wq, q, Mtot, Hv, Hv);
    gemm_tn<<<gg, blk, gemm_smem>>>(X, Wk, k, Mtot, Hv, Hv);
    gemm_tn<<<gg, blk, gemm_smem>>>(X, Wv, v, Mtot, Hv, Hv);

    dim3 ag(Sv / QT, NHv, Bv);       // (32, 16, 2)
    attn_kernel<<<ag, blk, attn_smem>>>();

    gemm_tn<<<gg, blk, gemm_smem>>>(o, Wo, out, Mtot, Hv, Hv);
}

// round 3
// speedup vs baseline: 1.1634x; 1.1634x over previous
#include <cuda_runtime.h>
#include <mma.h>
#include <cstdint>
#include <cstddef>

using namespace nvcuda;

#define Bv   2
#define Sv   2048
#define Hv   2048
#define NHv  16
#define HDv  128
#define BSv  256
#define Mtot (Bv * Sv)
#define ATT_SCALE 0.08838834764831843f  // 1/sqrt(128)

// ---------------- scratch (__device__ globals, allocation-free rule) -------
__device__ float g_q[(size_t)Mtot * Hv];
__device__ float g_k[(size_t)Mtot * Hv];
__device__ float g_v[(size_t)Mtot * Hv];
__device__ float g_o[(size_t)Mtot * Hv];
__device__ float g_xr[(size_t)Mtot * Hv];
__device__ float g_wq[(size_t)Hv * Hv];
__device__ float g_wk[(size_t)Hv * Hv];
__device__ float g_wv[(size_t)Hv * Hv];
__device__ float g_wo[(size_t)Hv * Hv];

// ---------------- helpers ---------------------------------------------------
__device__ __forceinline__ float to_tf32(float x) {
    float y;
    asm("cvt.rna.tf32.f32 %0, %1;" : "=f"(y) : "f"(x));
    return y;
}

__device__ __forceinline__ uint32_t smem_u32(const void* p) {
    uint32_t a;
    asm("{ .reg .u64 t; cvta.to.shared.u64 t, %1; cvt.u32.u64 %0, t; }" : "=r"(a) : "l"(p));
    return a;
}

__device__ __forceinline__ void cp_async16(uint32_t saddr, const void* gptr) {
    asm volatile("cp.async.cg.shared.global [%0], [%1], 16;" :: "r"(saddr), "l"(gptr));
}
#define CP_COMMIT() asm volatile("cp.async.commit_group;")
#define CP_WAIT(n)  asm volatile("cp.async.wait_group %0;" :: "n"(n))

// ---------------- rounding pre-pass ----------------------------------------
__global__ void __launch_bounds__(256) round_tf32_k(
    const float4* __restrict__ s, float4* __restrict__ d, int n4)
{
    int i = blockIdx.x * 256 + threadIdx.x;
    if (i < n4) {
        float4 v = s[i];
        v.x = to_tf32(v.x); v.y = to_tf32(v.y);
        v.z = to_tf32(v.z); v.w = to_tf32(v.w);
        d[i] = v;
    }
}

// ===========================================================================
// Pipelined tf32 wmma GEMM: C[M,N] = A[M,K] @ Bw[N,K]^T (K-major, pre-rounded)
// Tile 128x128x32, 4-stage cp.async, 256 threads (8 warps 4x2), fragment
// double-buffering in the BK loop.
// ===========================================================================
#define BM 128
#define BN 128
#define BK 32
#define STR 40                      // 32 + 8 pad floats; 160B rows (16B-aligned)
#define NSTG 4
#define A_FLTS (BM * STR)           // 5120 floats
#define STAGE_FLTS (2 * A_FLTS)     // A + B
#define GEMM_SMEM (NSTG * STAGE_FLTS * 4)   // 163840 B

__device__ __forceinline__ void stage_load(
    float* stg, const float* __restrict__ Ag, const float* __restrict__ Bg,
    int K, int tid)
{
#pragma unroll
    for (int i = 0; i < 4; i++) {      // A: 128 rows x 8 x 16B
        int id = tid + i * 256;
        int r = id >> 3, c = id & 7;
        cp_async16(smem_u32(stg + r * STR + c * 4), Ag + (size_t)r * K + c * 4);
    }
#pragma unroll
    for (int i = 0; i < 4; i++) {      // B: 128 rows x 8 x 16B
        int id = tid + i * 256;
        int r = id >> 3, c = id & 7;
        cp_async16(smem_u32(stg + A_FLTS + r * STR + c * 4), Bg + (size_t)r * K + c * 4);
    }
}

__global__ void __launch_bounds__(256, 1) gemm_pipe(
    const float* __restrict__ A, const float* __restrict__ Bw,
    float* __restrict__ C, int M, int N, int K)
{
    extern __shared__ __align__(16) float sm[];

    const int tid = threadIdx.x;
    const int wid = tid >> 5;
    const int m0 = blockIdx.y * BM;
    const int n0 = blockIdx.x * BN;
    const int wm = wid & 3;    // 4 warp rows x 32 m
    const int wn = wid >> 2;   // 2 warp cols x 64 n

    const float* Abase = A + (size_t)m0 * K;
    const float* Bbase = Bw + (size_t)n0 * K;
    const int KT = K / BK;

    wmma::fragment<wmma::accumulator, 16, 16, 8, float> acc[2][4];
#pragma unroll
    for (int i = 0; i < 2; i++)
#pragma unroll
        for (int j = 0; j < 4; j++) wmma::fill_fragment(acc[i][j], 0.0f);

    // prologue: stages 0..NSTG-2 <- k-tiles 0..NSTG-2
#pragma unroll
    for (int t = 0; t < NSTG - 1; t++) {
        stage_load(sm + t * STAGE_FLTS, Abase + t * BK, Bbase + t * BK, K, tid);
        CP_COMMIT();
    }

    for (int kt = 0; kt < KT; kt++) {
        CP_WAIT(NSTG - 2);          // k-tile kt resident
        __syncthreads();

        // prefetch k-tile kt+NSTG-1 into the stage freed at iteration kt-1
        int tn = kt + NSTG - 1;
        if (tn < KT)
            stage_load(sm + (tn % NSTG) * STAGE_FLTS, Abase + (size_t)tn * BK,
                       Bbase + (size_t)tn * BK, K, tid);
        CP_COMMIT();

        const float* sA = sm + (kt % NSTG) * STAGE_FLTS;
        const float* sB = sA + A_FLTS;

        wmma::fragment<wmma::matrix_a, 16, 16, 8, wmma::precision::tf32, wmma::row_major> af[2][2];
        wmma::fragment<wmma::matrix_b, 16, 16, 8, wmma::precision::tf32, wmma::col_major> bf[2][4];

#pragma unroll
        for (int i = 0; i < 2; i++)
            wmma::load_matrix_sync(af[0][i], sA + (wm * 32 + i * 16) * STR, STR);
#pragma unroll
        for (int j = 0; j < 4; j++)
            wmma::load_matrix_sync(bf[0][j], sB + (wn * 64 + j * 16) * STR, STR);

#pragma unroll
        for (int kk = 0; kk < 4; kk++) {
            int cb = kk & 1, nb = cb ^ 1;
            if (kk < 3) {
#pragma unroll
                for (int i = 0; i < 2; i++)
                    wmma::load_matrix_sync(af[nb][i], sA + (wm * 32 + i * 16) * STR + (kk + 1) * 8, STR);
#pragma unroll
                for (int j = 0; j < 4; j++)
                    wmma::load_matrix_sync(bf[nb][j], sB + (wn * 64 + j * 16) * STR + (kk + 1) * 8, STR);
            }
#pragma unroll
            for (int j = 0; j < 4; j++)
#pragma unroll
                for (int i = 0; i < 2; i++)
                    wmma::mma_sync(acc[i][j], af[cb][i], bf[cb][j], acc[i][j]);
        }
        __syncthreads();   // everyone done with stage kt%NSTG before it is refilled
    }

#pragma unroll
    for (int i = 0; i < 2; i++)
#pragma unroll
        for (int j = 0; j < 4; j++)
            wmma::store_matrix_sync(
                C + (size_t)(m0 + wm * 32 + i * 16) * N + n0 + wn * 64 + j * 16,
                acc[i][j], N, wmma::mem_row_major);
}

// ===========================================================================
// Attention with per-block softmax (unchanged, known-correct; epilogue
// tf32-rounds g_o so the Wo GEMM needs no conversion).
// ===========================================================================
#define QT  64
#define AST 136
#define SST 264

__global__ void __launch_bounds__(256) attn_kernel()
{
    extern __shared__ __align__(16) float sm[];
    float* shQ  = sm;
    float* shKV = shQ + QT * AST;
    float* shS  = shKV + QT * AST;

    const int tid = threadIdx.x;
    const int wid = tid >> 5;
    const int qt = blockIdx.x;
    const int h  = blockIdx.y;
    const int b  = blockIdx.z;
    const int qbase = qt * QT;
    const int bi = qbase >> 8;

    const float* Qp = g_q + ((size_t)b * Sv + qbase) * Hv + h * HDv;
#pragma unroll
    for (int i = 0; i < 8; i++) {
        int slot = tid + i * 256;
        int r = slot >> 5, c4 = slot & 31;
        float4 v = *(const float4*)(Qp + (size_t)r * Hv + c4 * 4);
        float* d = shQ + r * AST + c4 * 4;
        d[0] = to_tf32(v.x); d[1] = to_tf32(v.y);
        d[2] = to_tf32(v.z); d[3] = to_tf32(v.w);
    }

    wmma::fragment<wmma::accumulator, 16, 16, 8, float> acc_o[2][2];
#pragma unroll
    for (int i = 0; i < 2; i++)
#pragma unroll
        for (int j = 0; j < 2; j++) wmma::fill_fragment(acc_o[i][j], 0.0f);

    const int wms = wid & 3,  wns = wid >> 2;
    const int wmo = wid & 1,  wno = wid >> 1;

    const int row  = tid >> 2;
    const int part = tid & 3;
    const int qoff = (qbase & 255) + row;

    for (int jb = 0; jb <= bi; jb++) {
        for (int sub = 0; sub < 4; sub++) {
            __syncthreads();
            const float* Kp = g_k + ((size_t)b * Sv + jb * BSv + sub * 64) * Hv + h * HDv;
#pragma unroll
            for (int i = 0; i < 8; i++) {
                int slot = tid + i * 256;
                int r = slot >> 5, c4 = slot & 31;
                float4 v = *(const float4*)(Kp + (size_t)r * Hv + c4 * 4);
                float* d = shKV + r * AST + c4 * 4;
                d[0] = to_tf32(v.x); d[1] = to_tf32(v.y);
                d[2] = to_tf32(v.z); d[3] = to_tf32(v.w);
            }
            __syncthreads();

            wmma::fragment<wmma::accumulator, 16, 16, 8, float> accs[2];
            wmma::fill_fragment(accs[0], 0.0f);
            wmma::fill_fragment(accs[1], 0.0f);
#pragma unroll
            for (int k = 0; k < HDv; k += 8) {
                wmma::fragment<wmma::matrix_a, 16, 16, 8, wmma::precision::tf32, wmma::row_major> af;
                wmma::load_matrix_sync(af, shQ + (wms * 16) * AST + k, AST);
#pragma unroll
                for (int j = 0; j < 2; j++) {
                    wmma::fragment<wmma::matrix_b, 16, 16, 8, wmma::precision::tf32, wmma::col_major> bf;
                    wmma::load_matrix_sync(bf, shKV + (wns * 32 + j * 16) * AST + k, AST);
                    wmma::mma_sync(accs[j], af, bf, accs[j]);
                }
            }
#pragma unroll
            for (int j = 0; j < 2; j++)
                wmma::store_matrix_sync(
                    shS + (wms * 16) * SST + sub * 64 + wns * 32 + j * 16,
                    accs[j], SST, wmma::mem_row_major);
        }
        __syncthreads();

        {
            float* srow = shS + row * SST + part * 64;
            const bool diag = (jb == bi);
            const int cbase = part * 64;

            float mx = -3.0e38f;
#pragma unroll 8
            for (int c = 0; c < 64; c++) {
                bool masked = diag && (cbase + c > qoff);
                float s = srow[c];
                if (!masked) mx = fmaxf(mx, s);
            }
            mx = fmaxf(mx, __shfl_xor_sync(0xffffffffu, mx, 1));
            mx = fmaxf(mx, __shfl_xor_sync(0xffffffffu, mx, 2));
            mx *= ATT_SCALE;

            float sumv = 0.0f;
#pragma unroll 8
            for (int c = 0; c < 64; c++) {
                bool masked = diag && (cbase + c > qoff);
                float p = masked ? 0.0f : __expf(srow[c] * ATT_SCALE - mx);
                srow[c] = p;
                sumv += p;
            }
            sumv += __shfl_xor_sync(0xffffffffu, sumv, 1);
            sumv += __shfl_xor_sync(0xffffffffu, sumv, 2);
            float inv = 1.0f / sumv;
#pragma unroll 8
            for (int c = 0; c < 64; c++) srow[c] = to_tf32(srow[c] * inv);
        }

        for (int sub = 0; sub < 4; sub++) {
            __syncthreads();
            const float* Vp = g_v + ((size_t)b * Sv + jb * BSv + sub * 64) * Hv + h * HDv;
#pragma unroll
            for (int i = 0; i < 8; i++) {
                int slot = tid + i * 256;
                int r = slot >> 5, c4 = slot & 31;
                float4 v = *(const float4*)(Vp + (size_t)r * Hv + c4 * 4);
                float* d = shKV + r * AST + c4 * 4;
                d[0] = to_tf32(v.x); d[1] = to_tf32(v.y);
                d[2] = to_tf32(v.z); d[3] = to_tf32(v.w);
            }
            __syncthreads();

#pragma unroll
            for (int k = 0; k < 64; k += 8) {
                wmma::fragment<wmma::matrix_a, 16, 16, 8, wmma::precision::tf32, wmma::row_major> af[2];
#pragma unroll
                for (int i = 0; i < 2; i++)
                    wmma::load_matrix_sync(af[i], shS + (wmo * 32 + i * 16) * SST + sub * 64 + k, SST);
#pragma unroll
                for (int j = 0; j < 2; j++) {
                    wmma::fragment<wmma::matrix_b, 16, 16, 8, wmma::precision::tf32, wmma::row_major> bf;
                    wmma::load_matrix_sync(bf, shKV + k * AST + wno * 32 + j * 16, AST);
#pragma unroll
                    for (int i = 0; i < 2; i++)
                        wmma::mma_sync(acc_o[i][j], af[i], bf, acc_o[i][j]);
                }
            }
        }
    }

    const float invc = 1.0f / ((float)(bi + 1) + 1e-6f);
#pragma unroll
    for (int i = 0; i < 2; i++)
#pragma unroll
        for (int j = 0; j < 2; j++) {
#pragma unroll
            for (int t = 0; t < acc_o[i][j].num_elements; t++)
                acc_o[i][j].x[t] = to_tf32(acc_o[i][j].x[t] * invc);
            wmma::store_matrix_sync(
                g_o + ((size_t)(b * Sv + qbase + wmo * 32 + i * 16)) * Hv + h * HDv + wno * 32 + j * 16,
                acc_o[i][j], Hv, wmma::mem_row_major);
        }
}

// ===========================================================================
// launch
// ===========================================================================
extern "C" void kernel_launch(void* const* d_in, const int* in_sizes, int n_in,
                              void* d_out, int out_size)
{
    const float* X  = (const float*)d_in[0];
    const float* Wq = (const float*)d_in[1];
    const float* Wk = (const float*)d_in[2];
    const float* Wv = (const float*)d_in[3];
    const float* Wo = (const float*)d_in[4];
    float* out = (float*)d_out;

    float *q, *k, *v, *o, *xr, *wq, *wk, *wv, *wo;
    cudaGetSymbolAddress((void**)&q,  g_q);
    cudaGetSymbolAddress((void**)&k,  g_k);
    cudaGetSymbolAddress((void**)&v,  g_v);
    cudaGetSymbolAddress((void**)&o,  g_o);
    cudaGetSymbolAddress((void**)&xr, g_xr);
    cudaGetSymbolAddress((void**)&wq, g_wq);
    cudaGetSymbolAddress((void**)&wk, g_wk);
    cudaGetSymbolAddress((void**)&wv, g_wv);
    cudaGetSymbolAddress((void**)&wo, g_wo);

    const size_t attn_smem = (size_t)(2 * QT * AST + QT * SST) * sizeof(float);

    cudaFuncSetAttribute(gemm_pipe, cudaFuncAttributeMaxDynamicSharedMemorySize, GEMM_SMEM);
    cudaFuncSetAttribute(attn_kernel, cudaFuncAttributeMaxDynamicSharedMemorySize, (int)attn_smem);

    // RNA-round inputs to tf32 once; mma's tf32 truncation then becomes exact.
    const int nX4 = Mtot * Hv / 4;
    const int nW4 = Hv * Hv / 4;
    round_tf32_k<<<(nX4 + 255) / 256, 256>>>((const float4*)X,  (float4*)xr, nX4);
    round_tf32_k<<<(nW4 + 255) / 256, 256>>>((const float4*)Wq, (float4*)wq, nW4);
    round_tf32_k<<<(nW4 + 255) / 256, 256>>>((const float4*)Wk, (float4*)wk, nW4);
    round_tf32_k<<<(nW4 + 255) / 256, 256>>>((const float4*)Wv, (float4*)wv, nW4);
    round_tf32_k<<<(nW4 + 255) / 256, 256>>>((const float4*)Wo, (float4*)wo, nW4);

    dim3 gg(Hv / BN, Mtot / BM);     // (16, 32)
    gemm_pipe<<<gg, 256, GEMM_SMEM>>>(xr, wq, q, Mtot, Hv, Hv);
    gemm_pipe<<<gg, 256, GEMM_SMEM>>>(xr, wk, k, Mtot, Hv, Hv);
    gemm_pipe<<<gg, 256, GEMM_SMEM>>>(xr, wv, v, Mtot, Hv, Hv);

    dim3 ag(Sv / QT, NHv, Bv);       // (32, 16, 2)
    attn_kernel<<<ag, 256, attn_smem>>>();

    gemm_pipe<<<gg, 256, GEMM_SMEM>>>(o, wo, out, Mtot, Hv, Hv);
}

// round 4
// speedup vs baseline: 1.3985x; 1.2020x over previous
#include <cuda_runtime.h>
#include <mma.h>
#include <cstdint>
#include <cstddef>

using namespace nvcuda;

#define Bv   2
#define Sv   2048
#define Hv   2048
#define NHv  16
#define HDv  128
#define BSv  256
#define Mtot (Bv * Sv)
#define ATT_SCALE 0.08838834764831843f  // 1/sqrt(128)

// ---------------- scratch (__device__ globals, allocation-free rule) -------
__device__ float g_q[(size_t)Mtot * Hv];
__device__ float g_k[(size_t)Mtot * Hv];
__device__ float g_v[(size_t)Mtot * Hv];
__device__ float g_o[(size_t)Mtot * Hv];
__device__ float g_xr[(size_t)Mtot * Hv];
__device__ float g_wq[(size_t)Hv * Hv];
__device__ float g_wk[(size_t)Hv * Hv];
__device__ float g_wv[(size_t)Hv * Hv];
__device__ float g_wo[(size_t)Hv * Hv];

// ---------------- helpers ---------------------------------------------------
__device__ __forceinline__ float to_tf32(float x) {
    float y;
    asm("cvt.rna.tf32.f32 %0, %1;" : "=f"(y) : "f"(x));
    return y;
}

__device__ __forceinline__ uint32_t smem_u32(const void* p) {
    uint32_t a;
    asm("{ .reg .u64 t; cvta.to.shared.u64 t, %1; cvt.u32.u64 %0, t; }" : "=r"(a) : "l"(p));
    return a;
}

__device__ __forceinline__ void cp_async16(uint32_t saddr, const void* gptr) {
    asm volatile("cp.async.cg.shared.global [%0], [%1], 16;" :: "r"(saddr), "l"(gptr));
}
#define CP_COMMIT() asm volatile("cp.async.commit_group;")
#define CP_WAIT(n)  asm volatile("cp.async.wait_group %0;" :: "n"(n))

// ---------------- rounding pre-pass ----------------------------------------
__global__ void __launch_bounds__(256) round_tf32_k(
    const float4* __restrict__ s, float4* __restrict__ d, int n4)
{
    int i = blockIdx.x * 256 + threadIdx.x;
    if (i < n4) {
        float4 v = s[i];
        v.x = to_tf32(v.x); v.y = to_tf32(v.y);
        v.z = to_tf32(v.z); v.w = to_tf32(v.w);
        d[i] = v;
    }
}

// ===========================================================================
// Pipelined tf32 wmma GEMM: C[M,N] = A[M,K] @ Bw[N,K]^T (K-major, pre-rounded)
// CTA tile 256x128x32, 8 warps (4x2) with 64x64 warp tiles, 4-stage cp.async.
// do_round=1 -> epilogue RNA-rounds C to tf32 (for Q/K/V feeding attention).
// ===========================================================================
#define BM 256
#define BN 128
#define BK 32
#define STR 36                       // 32 + 4 pad floats; 144B rows (16B-aligned)
#define NSTG 4
#define A_FLTS (BM * STR)            // 9216
#define B_FLTS (BN * STR)            // 4608
#define STAGE_FLTS (A_FLTS + B_FLTS) // 13824
#define GEMM_SMEM (NSTG * STAGE_FLTS * 4)   // 221184 B

__device__ __forceinline__ void stage_load(
    float* stg, const float* __restrict__ Ag, const float* __restrict__ Bg,
    int K, int tid)
{
#pragma unroll
    for (int i = 0; i < 8; i++) {      // A: 256 rows x 8 x 16B
        int id = tid + i * 256;
        int r = id >> 3, c = id & 7;
        cp_async16(smem_u32(stg + r * STR + c * 4), Ag + (size_t)r * K + c * 4);
    }
#pragma unroll
    for (int i = 0; i < 4; i++) {      // B: 128 rows x 8 x 16B
        int id = tid + i * 256;
        int r = id >> 3, c = id & 7;
        cp_async16(smem_u32(stg + A_FLTS + r * STR + c * 4), Bg + (size_t)r * K + c * 4);
    }
}

__global__ void __launch_bounds__(256, 1) gemm_pipe(
    const float* __restrict__ A, const float* __restrict__ Bw,
    float* __restrict__ C, int M, int N, int K, int do_round)
{
    extern __shared__ __align__(16) float sm[];

    const int tid = threadIdx.x;
    const int wid = tid >> 5;
    const int m0 = blockIdx.y * BM;
    const int n0 = blockIdx.x * BN;
    const int wm = wid & 3;    // 4 warp rows x 64 m
    const int wn = wid >> 2;   // 2 warp cols x 64 n

    const float* Abase = A + (size_t)m0 * K;
    const float* Bbase = Bw + (size_t)n0 * K;
    const int KT = K / BK;

    wmma::fragment<wmma::accumulator, 16, 16, 8, float> acc[4][4];
#pragma unroll
    for (int i = 0; i < 4; i++)
#pragma unroll
        for (int j = 0; j < 4; j++) wmma::fill_fragment(acc[i][j], 0.0f);

    // prologue: stages 0..NSTG-2 <- k-tiles 0..NSTG-2
#pragma unroll
    for (int t = 0; t < NSTG - 1; t++) {
        stage_load(sm + t * STAGE_FLTS, Abase + t * BK, Bbase + t * BK, K, tid);
        CP_COMMIT();
    }

    for (int kt = 0; kt < KT; kt++) {
        CP_WAIT(NSTG - 2);          // k-tile kt resident
        __syncthreads();            // also fences reads of the stage refilled below

        int tn = kt + NSTG - 1;
        if (tn < KT)
            stage_load(sm + (tn % NSTG) * STAGE_FLTS, Abase + (size_t)tn * BK,
                       Bbase + (size_t)tn * BK, K, tid);
        CP_COMMIT();

        const float* sA = sm + (kt % NSTG) * STAGE_FLTS;
        const float* sB = sA + A_FLTS;

#pragma unroll
        for (int kk = 0; kk < 4; kk++) {
            wmma::fragment<wmma::matrix_a, 16, 16, 8, wmma::precision::tf32, wmma::row_major> af[4];
            wmma::fragment<wmma::matrix_b, 16, 16, 8, wmma::precision::tf32, wmma::col_major> bf[4];
#pragma unroll
            for (int i = 0; i < 4; i++)
                wmma::load_matrix_sync(af[i], sA + (wm * 64 + i * 16) * STR + kk * 8, STR);
#pragma unroll
            for (int j = 0; j < 4; j++)
                wmma::load_matrix_sync(bf[j], sB + (wn * 64 + j * 16) * STR + kk * 8, STR);
#pragma unroll
            for (int j = 0; j < 4; j++)
#pragma unroll
                for (int i = 0; i < 4; i++)
                    wmma::mma_sync(acc[i][j], af[i], bf[j], acc[i][j]);
        }
    }

#pragma unroll
    for (int i = 0; i < 4; i++)
#pragma unroll
        for (int j = 0; j < 4; j++) {
            if (do_round) {
#pragma unroll
                for (int t = 0; t < acc[i][j].num_elements; t++)
                    acc[i][j].x[t] = to_tf32(acc[i][j].x[t]);
            }
            wmma::store_matrix_sync(
                C + (size_t)(m0 + wm * 64 + i * 16) * N + n0 + wn * 64 + j * 16,
                acc[i][j], N, wmma::mem_row_major);
        }
}

// ===========================================================================
// Attention with per-block softmax. Q/K/V are pre-rounded to tf32 by the
// projection GEMM epilogue, so cp.async moves them straight to smem.
// K/V subtiles double-buffered; loads always one subtile ahead.
// ===========================================================================
#define QT  64
#define AST 132   // 128 + 4 pad (528B rows: 16B-aligned, 2-way-conflict stride)
#define SST 260   // 256 + 4 pad

__global__ void __launch_bounds__(256) attn_kernel()
{
    extern __shared__ __align__(16) float sm[];
    float* shQ  = sm;                          // [64][AST]
    float* shKV[2] = { shQ + QT * AST, shQ + 2 * QT * AST };
    float* shS  = shQ + 3 * QT * AST;          // [64][SST]

    const int tid = threadIdx.x;
    const int wid = tid >> 5;
    const int qt = blockIdx.x;
    const int h  = blockIdx.y;
    const int b  = blockIdx.z;
    const int qbase = qt * QT;
    const int bi = qbase >> 8;

    const float* Qp    = g_q + ((size_t)b * Sv + qbase) * Hv + h * HDv;
    const float* Kbase = g_k + ((size_t)b * Sv) * Hv + h * HDv;
    const float* Vbase = g_v + ((size_t)b * Sv) * Hv + h * HDv;

    // 64x128 async tile load, row stride Hv in gmem, AST in smem
    auto load64 = [&](float* dst, const float* src) {
#pragma unroll
        for (int i = 0; i < 8; i++) {
            int id = tid + i * 256;
            int r = id >> 5, c4 = id & 31;
            cp_async16(smem_u32(dst + r * AST + c4 * 4), src + (size_t)r * Hv + c4 * 4);
        }
    };

    load64(shQ, Qp);
    load64(shKV[0], Kbase);   // K(jb=0, sub=0)
    CP_COMMIT();

    wmma::fragment<wmma::accumulator, 16, 16, 8, float> acc_o[2][2];
#pragma unroll
    for (int i = 0; i < 2; i++)
#pragma unroll
        for (int j = 0; j < 2; j++) wmma::fill_fragment(acc_o[i][j], 0.0f);

    const int wms = wid & 3,  wns = wid >> 2;   // S phase: 16 rows x 32 cols
    const int wmo = wid & 1,  wno = wid >> 1;   // O phase: 32 rows x 32 cols

    const int row  = tid >> 2;
    const int part = tid & 3;
    const int qoff = (qbase & 255) + row;

    for (int jb = 0; jb <= bi; jb++) {
        const float* Kj = Kbase + (size_t)jb * BSv * Hv;
        const float* Vj = Vbase + (size_t)jb * BSv * Hv;

        // ---- S phase: 4 subtiles of 64 keys ----
        for (int s = 0; s < 4; s++) {
            CP_WAIT(0);
            __syncthreads();
            if (s < 3)       load64(shKV[(s + 1) & 1], Kj + (size_t)(s + 1) * 64 * Hv);
            else             load64(shKV[0],           Vj);            // V(jb,0)
            CP_COMMIT();

            const float* kb = shKV[s & 1];
            wmma::fragment<wmma::accumulator, 16, 16, 8, float> accs[2];
            wmma::fill_fragment(accs[0], 0.0f);
            wmma::fill_fragment(accs[1], 0.0f);
#pragma unroll
            for (int k = 0; k < HDv; k += 8) {
                wmma::fragment<wmma::matrix_a, 16, 16, 8, wmma::precision::tf32, wmma::row_major> af;
                wmma::load_matrix_sync(af, shQ + (wms * 16) * AST + k, AST);
#pragma unroll
                for (int j = 0; j < 2; j++) {
                    wmma::fragment<wmma::matrix_b, 16, 16, 8, wmma::precision::tf32, wmma::col_major> bf;
                    wmma::load_matrix_sync(bf, kb + (wns * 32 + j * 16) * AST + k, AST);
                    wmma::mma_sync(accs[j], af, bf, accs[j]);
                }
            }
#pragma unroll
            for (int j = 0; j < 2; j++)
                wmma::store_matrix_sync(
                    shS + (wms * 16) * SST + s * 64 + wns * 32 + j * 16,
                    accs[j], SST, wmma::mem_row_major);
        }
        __syncthreads();   // S complete

        // ---- per-block softmax over 256 keys (V0 load overlaps this) ----
        {
            float* srow = shS + row * SST + part * 64;
            const bool diag = (jb == bi);
            const int cbase = part * 64;

            float mx = -3.0e38f;
#pragma unroll 8
            for (int c = 0; c < 64; c++) {
                bool masked = diag && (cbase + c > qoff);
                float s = srow[c];
                if (!masked) mx = fmaxf(mx, s);
            }
            mx = fmaxf(mx, __shfl_xor_sync(0xffffffffu, mx, 1));
            mx = fmaxf(mx, __shfl_xor_sync(0xffffffffu, mx, 2));
            mx *= ATT_SCALE;

            float sumv = 0.0f;
#pragma unroll 8
            for (int c = 0; c < 64; c++) {
                bool masked = diag && (cbase + c > qoff);
                float p = masked ? 0.0f : __expf(srow[c] * ATT_SCALE - mx);
                srow[c] = p;
                sumv += p;
            }
            sumv += __shfl_xor_sync(0xffffffffu, sumv, 1);
            sumv += __shfl_xor_sync(0xffffffffu, sumv, 2);
            float inv = 1.0f / sumv;
#pragma unroll 8
            for (int c = 0; c < 64; c++) srow[c] = to_tf32(srow[c] * inv);
        }

        // ---- PV phase: 4 subtiles of 64 kv rows ----
        for (int v = 0; v < 4; v++) {
            CP_WAIT(0);
            __syncthreads();    // also orders softmax writes before PV reads
            if (v < 3)          load64(shKV[(v + 1) & 1], Vj + (size_t)(v + 1) * 64 * Hv);
            else if (jb < bi)   load64(shKV[0], Kj + (size_t)BSv * Hv);  // K(jb+1,0)
            CP_COMMIT();

            const float* vb = shKV[v & 1];
#pragma unroll
            for (int k = 0; k < 64; k += 8) {
                wmma::fragment<wmma::matrix_a, 16, 16, 8, wmma::precision::tf32, wmma::row_major> af[2];
#pragma unroll
                for (int i = 0; i < 2; i++)
                    wmma::load_matrix_sync(af[i], shS + (wmo * 32 + i * 16) * SST + v * 64 + k, SST);
#pragma unroll
                for (int j = 0; j < 2; j++) {
                    wmma::fragment<wmma::matrix_b, 16, 16, 8, wmma::precision::tf32, wmma::row_major> bf;
                    wmma::load_matrix_sync(bf, vb + k * AST + wno * 32 + j * 16, AST);
#pragma unroll
                    for (int i = 0; i < 2; i++)
                        wmma::mma_sync(acc_o[i][j], af[i], bf, acc_o[i][j]);
                }
            }
        }
    }

    // ---- epilogue: divide by block count, tf32-round, store merged layout ----
    const float invc = 1.0f / ((float)(bi + 1) + 1e-6f);
#pragma unroll
    for (int i = 0; i < 2; i++)
#pragma unroll
        for (int j = 0; j < 2; j++) {
#pragma unroll
            for (int t = 0; t < acc_o[i][j].num_elements; t++)
                acc_o[i][j].x[t] = to_tf32(acc_o[i][j].x[t] * invc);
            wmma::store_matrix_sync(
                g_o + ((size_t)(b * Sv + qbase + wmo * 32 + i * 16)) * Hv + h * HDv + wno * 32 + j * 16,
                acc_o[i][j], Hv, wmma::mem_row_major);
        }
}

// ===========================================================================
// launch
// ===========================================================================
extern "C" void kernel_launch(void* const* d_in, const int* in_sizes, int n_in,
                              void* d_out, int out_size)
{
    const float* X  = (const float*)d_in[0];
    const float* Wq = (const float*)d_in[1];
    const float* Wk = (const float*)d_in[2];
    const float* Wv = (const float*)d_in[3];
    const float* Wo = (const float*)d_in[4];
    float* out = (float*)d_out;

    float *q, *k, *v, *o, *xr, *wq, *wk, *wv, *wo;
    cudaGetSymbolAddress((void**)&q,  g_q);
    cudaGetSymbolAddress((void**)&k,  g_k);
    cudaGetSymbolAddress((void**)&v,  g_v);
    cudaGetSymbolAddress((void**)&o,  g_o);
    cudaGetSymbolAddress((void**)&xr, g_xr);
    cudaGetSymbolAddress((void**)&wq, g_wq);
    cudaGetSymbolAddress((void**)&wk, g_wk);
    cudaGetSymbolAddress((void**)&wv, g_wv);
    cudaGetSymbolAddress((void**)&wo, g_wo);

    const size_t attn_smem = (size_t)(3 * QT * AST + QT * SST) * sizeof(float);  // 167936

    cudaFuncSetAttribute(gemm_pipe, cudaFuncAttributeMaxDynamicSharedMemorySize, GEMM_SMEM);
    cudaFuncSetAttribute(attn_kernel, cudaFuncAttributeMaxDynamicSharedMemorySize, (int)attn_smem);

    // RNA-round inputs to tf32 once; mma's tf32 truncation then becomes exact.
    const int nX4 = Mtot * Hv / 4;
    const int nW4 = Hv * Hv / 4;
    round_tf32_k<<<(nX4 + 255) / 256, 256>>>((const float4*)X,  (float4*)xr, nX4);
    round_tf32_k<<<(nW4 + 255) / 256, 256>>>((const float4*)Wq, (float4*)wq, nW4);
    round_tf32_k<<<(nW4 + 255) / 256, 256>>>((const float4*)Wk, (float4*)wk, nW4);
    round_tf32_k<<<(nW4 + 255) / 256, 256>>>((const float4*)Wv, (float4*)wv, nW4);
    round_tf32_k<<<(nW4 + 255) / 256, 256>>>((const float4*)Wo, (float4*)wo, nW4);

    dim3 gg(Hv / BN, Mtot / BM);     // (16, 16)
    gemm_pipe<<<gg, 256, GEMM_SMEM>>>(xr, wq, q, Mtot, Hv, Hv, 1);
    gemm_pipe<<<gg, 256, GEMM_SMEM>>>(xr, wk, k, Mtot, Hv, Hv, 1);
    gemm_pipe<<<gg, 256, GEMM_SMEM>>>(xr, wv, v, Mtot, Hv, Hv, 1);

    dim3 ag(Sv / QT, NHv, Bv);       // (32, 16, 2)
    attn_kernel<<<ag, 256, attn_smem>>>();

    gemm_pipe<<<gg, 256, GEMM_SMEM>>>(o, wo, out, Mtot, Hv, Hv, 0);
}